// round 8
// baseline (speedup 1.0000x reference)
#include <cuda_runtime.h>
#include <stdint.h>

#define NSITES   144
#define NHID     256
#define G3       768
#define BATCH    1024
#define NB       8
#define NBLOCKS  (BATCH / NB)
#define THREADS  1024
#define NQ       4
#define KQ       (NHID / NQ)       // 64 k-iters per thread
#define SSTRIDE  12                // h_s row stride (floats), 48B rows

// ---------------- threefry2x32 core (JAX schedule) ----------------
__device__ __forceinline__ uint32_t rotl32(uint32_t x, uint32_t r) {
    return __funnelshift_l(x, x, r);
}

__device__ __forceinline__ void tf2x32(uint32_t k0, uint32_t k1,
                                       uint32_t x0, uint32_t x1,
                                       uint32_t &o0, uint32_t &o1) {
    uint32_t k2 = k0 ^ k1 ^ 0x1BD11BDAu;
    x0 += k0; x1 += k1;
#define TFR(r) { x0 += x1; x1 = rotl32(x1, r); x1 ^= x0; }
    TFR(13) TFR(15) TFR(26) TFR(6)    x0 += k1; x1 += k2 + 1u;
    TFR(17) TFR(29) TFR(16) TFR(24)   x0 += k2; x1 += k0 + 2u;
    TFR(13) TFR(15) TFR(26) TFR(6)    x0 += k0; x1 += k1 + 3u;
    TFR(17) TFR(29) TFR(16) TFR(24)   x0 += k1; x1 += k2 + 4u;
    TFR(13) TFR(15) TFR(26) TFR(6)    x0 += k2; x1 += k0 + 5u;
#undef TFR
    o0 = x0; o1 = x1;
}

// Partitionable random_bits (32-bit): element i = w0 ^ w1 of tf2x32(key, (0, i))
__device__ __forceinline__ uint32_t rbits_part(uint32_t k0, uint32_t k1, uint32_t i) {
    uint32_t o0, o1;
    tf2x32(k0, k1, 0u, i, o0, o1);
    return o0 ^ o1;
}

// jax.random.gumbel: -log(-log(uniform(tiny, 1)))
__device__ __forceinline__ float gumbel_from(uint32_t bits) {
    const float TINY = 1.17549435e-38f;
    float f = __uint_as_float((bits >> 9) | 0x3f800000u) - 1.0f;
    float u = fmaxf(TINY, f + TINY);
    return -logf(-logf(u));
}

// ---------------- packed f32x2 ops (sm_100+) ----------------
__device__ __forceinline__ void fma2(unsigned long long &d, unsigned long long a,
                                     unsigned long long b) {
    asm("fma.rn.f32x2 %0, %1, %2, %0;" : "+l"(d) : "l"(a), "l"(b));
}
__device__ __forceinline__ unsigned long long pack2(float x) {
    unsigned long long r;
    asm("mov.b64 %0, {%1, %1};" : "=l"(r) : "f"(x));
    return r;
}
__device__ __forceinline__ unsigned long long add2(unsigned long long a,
                                                   unsigned long long b) {
    unsigned long long r;
    asm("add.rn.f32x2 %0, %1, %2;" : "=l"(r) : "l"(a), "l"(b));
    return r;
}
__device__ __forceinline__ void unpack2(unsigned long long v, float &lo, float &hi) {
    asm("mov.b64 {%0, %1}, %2;" : "=f"(lo), "=f"(hi) : "l"(v));
}

__device__ __forceinline__ float sigmoid_x(float x) {
    return 0.5f + 0.5f * tanhf(0.5f * x);
}

__global__ void __launch_bounds__(THREADS, 1)
rnn_sample_kernel(const float* __restrict__ Wx,    // kernel      [2, 768]
                  const float* __restrict__ Wh,    // rec_kernel  [256, 768]
                  const float* __restrict__ bias,  // [2, 768]
                  const float* __restrict__ Dw,    // dense_w     [256, 2]
                  const float* __restrict__ Db,    // dense_b     [2]
                  float* __restrict__ out)         // samples [1024,144] then logP [1024]
{
    __shared__ __align__(16) float h_s[NHID * SSTRIDE];   // 12 KB, [k][b]
    __shared__ float gx_s[3 * G3];                        // 9 KB: [x-case][col]
    __shared__ float gum[NSITES * NB * 2];                // 9 KB: [t][b][cls]
    __shared__ int s_arr[NB];

    const int tid  = threadIdx.x;
    const int lane = tid & 31;
    const int warp = tid >> 5;
    const int jg   = tid >> 2;       // gate unit 0..255
    const int q    = tid & 3;        // k-quarter AND sample-pair owner (adjacent lanes!)
    const int bbase = blockIdx.x * NB;

    // ---- one-time init ----
    for (int i = tid; i < NHID * SSTRIDE; i += THREADS) h_s[i] = 0.0f;
    for (int c = tid; c < G3; c += THREADS) {
        float b0 = bias[c];
        gx_s[c]          = b0;              // x = 0 (t=0)
        gx_s[G3 + c]     = Wx[c] + b0;      // one_hot(0)
        gx_s[2 * G3 + c] = Wx[G3 + c] + b0; // one_hot(1)
    }
    for (int i = tid; i < NSITES * NB * 2; i += THREADS) {
        int t = i >> 4, r = i & 15;
        int b = r >> 1, cls = r & 1;
        uint32_t o0, o1;
        tf2x32(0u, 42u, 0u, (uint32_t)t, o0, o1);       // step key (partitionable split)
        gum[i] = gumbel_from(rbits_part(o0, o1, (uint32_t)(2 * (bbase + b) + cls)));
    }
    if (tid < NB) s_arr[tid] = -1;
    float logP = 0.0f;   // lane 0 of warps 0..7 (sample = warp id)
    __syncthreads();

    const float b1z = bias[G3 + jg], b1r = bias[G3 + 256 + jg], b1n = bias[G3 + 512 + jg];
    const float db0 = Db[0], db1 = Db[1];
    const int k0 = q * KQ;

    for (int t = 0; t < NSITES; ++t) {
        // ---------- partial gh = h @ Wh over this thread's k-quarter ----------
        unsigned long long acc[12];
#pragma unroll
        for (int i = 0; i < 12; ++i) acc[i] = 0ull;
        const float* wp = Wh + k0 * G3 + jg;
#pragma unroll 4
        for (int k = k0; k < k0 + KQ; ++k) {
            unsigned long long w0 = pack2(wp[0]);
            unsigned long long w1 = pack2(wp[256]);
            unsigned long long w2 = pack2(wp[512]);
            wp += G3;
            const ulonglong2* hp = reinterpret_cast<const ulonglong2*>(h_s + k * SSTRIDE);
            ulonglong2 hA = hp[0], hB = hp[1];
            fma2(acc[0], w0, hA.x); fma2(acc[1], w0, hA.y);
            fma2(acc[2], w0, hB.x); fma2(acc[3], w0, hB.y);
            fma2(acc[4], w1, hA.x); fma2(acc[5], w1, hA.y);
            fma2(acc[6], w1, hB.x); fma2(acc[7], w1, hB.y);
            fma2(acc[8], w2, hA.x); fma2(acc[9], w2, hA.y);
            fma2(acc[10], w2, hB.x); fma2(acc[11], w2, hB.y);
        }

        // ---------- butterfly reduce across the 4 q-lanes (same warp) ----------
#pragma unroll
        for (int i = 0; i < 12; ++i) {
            acc[i] = add2(acc[i], __shfl_xor_sync(0xffffffffu, acc[i], 1));
            acc[i] = add2(acc[i], __shfl_xor_sync(0xffffffffu, acc[i], 2));
        }
        __syncthreads();   // all k-loop reads of old h complete before h update

        // ---------- gate math: lane q handles samples {2q, 2q+1} ----------
        {
            float gz[2], gr[2], gn[2];
            unpack2(acc[q],     gz[0], gz[1]);
            unpack2(acc[4 + q], gr[0], gr[1]);
            unpack2(acc[8 + q], gn[0], gn[1]);
#pragma unroll
            for (int u = 0; u < 2; ++u) {
                int b = 2 * q + u;
                int idx = s_arr[b] + 1;                 // -1 -> 0 (x = 0 at t=0)
                float gxz = gx_s[idx * G3 + jg];
                float gxr = gx_s[idx * G3 + 256 + jg];
                float gxn = gx_s[idx * G3 + 512 + jg];
                float z  = sigmoid_x(gxz + gz[u] + b1z);
                float r  = sigmoid_x(gxr + gr[u] + b1r);
                float hh = tanhf(gxn + r * (gn[u] + b1n));
                float hold = h_s[jg * SSTRIDE + b];
                h_s[jg * SSTRIDE + b] = z * hold + (1.0f - z) * hh;
            }
        }
        __syncthreads();

        // ---------- dense head + softmax + categorical (warp w -> sample w) ----------
        if (warp < NB) {
            const int b = warp;
            float c0 = 0.0f, c1 = 0.0f;
            for (int k = lane; k < NHID; k += 32) {
                float hv = h_s[k * SSTRIDE + b];
                c0 += hv * Dw[2 * k];
                c1 += hv * Dw[2 * k + 1];
            }
#pragma unroll
            for (int off = 16; off > 0; off >>= 1) {
                c0 += __shfl_down_sync(0xffffffffu, c0, off);
                c1 += __shfl_down_sync(0xffffffffu, c1, off);
            }
            if (lane == 0) {
                float la = c0 + db0, lb = c1 + db1;
                float m  = fmaxf(la, lb);
                float ea = expf(la - m), eb = expf(lb - m);
                float sm = ea + eb;
                float lp0 = logf(1e-10f + ea / sm);
                float lp1 = logf(1e-10f + eb / sm);
                float g0 = gum[(t * NB + b) * 2];
                float g1 = gum[(t * NB + b) * 2 + 1];
                int s = (g1 + lp1 > g0 + lp0) ? 1 : 0;   // argmax ties -> index 0
                logP += s ? lp1 : lp0;
                s_arr[b] = s;
                out[(bbase + b) * NSITES + t] = (float)s;
            }
        }
        __syncthreads();
    }

    if (warp < NB && lane == 0) {
        out[BATCH * NSITES + bbase + warp] = logP;
    }
}

extern "C" void kernel_launch(void* const* d_in, const int* in_sizes, int n_in,
                              void* d_out, int out_size) {
    (void)in_sizes; (void)n_in; (void)out_size;
    const float* Wx   = (const float*)d_in[0];
    const float* Wh   = (const float*)d_in[1];
    const float* bias = (const float*)d_in[2];
    const float* Dw   = (const float*)d_in[3];
    const float* Db   = (const float*)d_in[4];
    float* out = (float*)d_out;
    rnn_sample_kernel<<<NBLOCKS, THREADS>>>(Wx, Wh, bias, Dw, Db, out);
}

// round 9
// speedup vs baseline: 4.3318x; 4.3318x over previous
#include <cuda_runtime.h>
#include <stdint.h>

#define NSITES   144
#define NHID     256
#define G3       768
#define BATCH    1024
#define NB       8
#define NBLOCKS  (BATCH / NB)
#define THREADS  512
#define KHALF    128
#define HSTRIDE  8                 // h_s row stride (floats) == NB, 32B rows
#define RSTRIDE  7                 // red row stride (u64): 56B, 2-way conflicts max

// ---------------- threefry2x32 core (JAX schedule) ----------------
__device__ __forceinline__ uint32_t rotl32(uint32_t x, uint32_t r) {
    return __funnelshift_l(x, x, r);
}

__device__ __forceinline__ void tf2x32(uint32_t k0, uint32_t k1,
                                       uint32_t x0, uint32_t x1,
                                       uint32_t &o0, uint32_t &o1) {
    uint32_t k2 = k0 ^ k1 ^ 0x1BD11BDAu;
    x0 += k0; x1 += k1;
#define TFR(r) { x0 += x1; x1 = rotl32(x1, r); x1 ^= x0; }
    TFR(13) TFR(15) TFR(26) TFR(6)    x0 += k1; x1 += k2 + 1u;
    TFR(17) TFR(29) TFR(16) TFR(24)   x0 += k2; x1 += k0 + 2u;
    TFR(13) TFR(15) TFR(26) TFR(6)    x0 += k0; x1 += k1 + 3u;
    TFR(17) TFR(29) TFR(16) TFR(24)   x0 += k1; x1 += k2 + 4u;
    TFR(13) TFR(15) TFR(26) TFR(6)    x0 += k2; x1 += k0 + 5u;
#undef TFR
    o0 = x0; o1 = x1;
}

// Partitionable random_bits (32-bit): element i = w0 ^ w1 of tf2x32(key, (0, i))
__device__ __forceinline__ uint32_t rbits_part(uint32_t k0, uint32_t k1, uint32_t i) {
    uint32_t o0, o1;
    tf2x32(k0, k1, 0u, i, o0, o1);
    return o0 ^ o1;
}

// jax.random.gumbel: -log(-log(uniform(tiny, 1)))
__device__ __forceinline__ float gumbel_from(uint32_t bits) {
    const float TINY = 1.17549435e-38f;
    float f = __uint_as_float((bits >> 9) | 0x3f800000u) - 1.0f;
    float u = fmaxf(TINY, f + TINY);
    return -logf(-logf(u));
}

// ---------------- packed f32x2 ops (sm_100+) ----------------
__device__ __forceinline__ void fma2(unsigned long long &d, unsigned long long a,
                                     unsigned long long b) {
    asm("fma.rn.f32x2 %0, %1, %2, %0;" : "+l"(d) : "l"(a), "l"(b));
}
__device__ __forceinline__ unsigned long long pack2(float x) {
    unsigned long long r;
    asm("mov.b64 %0, {%1, %1};" : "=l"(r) : "f"(x));
    return r;
}
__device__ __forceinline__ unsigned long long add2(unsigned long long a,
                                                   unsigned long long b) {
    unsigned long long r;
    asm("add.rn.f32x2 %0, %1, %2;" : "=l"(r) : "l"(a), "l"(b));
    return r;
}
__device__ __forceinline__ void unpack2(unsigned long long v, float &lo, float &hi) {
    asm("mov.b64 {%0, %1}, %2;" : "=f"(lo), "=f"(hi) : "l"(v));
}

__device__ __forceinline__ float sigmoid_x(float x) {
    return 0.5f + 0.5f * tanhf(0.5f * x);
}

__global__ void __launch_bounds__(THREADS, 1)
rnn_sample_kernel(const float* __restrict__ Wx,    // kernel      [2, 768]
                  const float* __restrict__ Wh,    // rec_kernel  [256, 768]
                  const float* __restrict__ bias,  // [2, 768]
                  const float* __restrict__ Dw,    // dense_w     [256, 2]
                  const float* __restrict__ Db,    // dense_b     [2]
                  float* __restrict__ out)         // samples [1024,144] then logP [1024]
{
    __shared__ __align__(16) float h_s[NHID * HSTRIDE];               // 8 KB, [k][b]
    __shared__ __align__(16) unsigned long long red[2 * NHID * RSTRIDE]; // 28 KB
    __shared__ float gum[NSITES * NB * 2];                            // 9 KB
    __shared__ int s_arr[NB];

    const int tid  = threadIdx.x;
    const int lane = tid & 31;
    const int warp = tid >> 5;
    const int half = tid >> 8;       // 0: k in [0,128), samples 0-3; 1: k in [128,256), 4-7
    const int j    = tid & 255;      // gate unit / column
    const int bbase = blockIdx.x * NB;

    // ---- one-time init ----
    for (int i = tid; i < NHID * HSTRIDE; i += THREADS) h_s[i] = 0.0f;
    for (int i = tid; i < NSITES * NB * 2; i += THREADS) {
        int t = i >> 4, r = i & 15;
        int b = r >> 1, cls = r & 1;
        uint32_t o0, o1;
        tf2x32(0u, 42u, 0u, (uint32_t)t, o0, o1);       // partitionable split -> step key
        gum[i] = gumbel_from(rbits_part(o0, o1, (uint32_t)(2 * (bbase + b) + cls)));
    }
    if (tid < NB) s_arr[tid] = -1;
    float logP = 0.0f;   // lane 0 of warps 0..7 (sample = warp id)
    __syncthreads();

    // gate-input constants in registers (9): bias row 0 and bias0+Wx[s]
    const float b0z = bias[j],       b0r = bias[256 + j],  b0n = bias[512 + j];
    const float c0z = b0z + Wx[j],        c0r = b0r + Wx[256 + j],  c0n = b0n + Wx[512 + j];
    const float c1z = b0z + Wx[G3 + j],   c1r = b0r + Wx[G3 + 256 + j],
                c1n = b0n + Wx[G3 + 512 + j];
    const float b1z = bias[G3 + j], b1r = bias[G3 + 256 + j], b1n = bias[G3 + 512 + j];
    const float db0 = Db[0], db1 = Db[1];
    const int k0 = half * KHALF;
    const int op = 2 * half;                       // my sample-pair base
    unsigned long long* st = red + (half * NHID + j) * RSTRIDE;
    const unsigned long long* ld = red + ((1 - half) * NHID + j) * RSTRIDE;

    for (int i = 0; i < NSITES; ++i) {
        // ======== phase 1: k-loop (gh partials) ∥ head for step i-1 ========
        unsigned long long acc[12];
#pragma unroll
        for (int a = 0; a < 12; ++a) acc[a] = 0ull;
        const float* wp = Wh + k0 * G3 + j;
#pragma unroll 8
        for (int k = k0; k < k0 + KHALF; ++k) {
            unsigned long long w0 = pack2(wp[0]);
            unsigned long long w1 = pack2(wp[256]);
            unsigned long long w2 = pack2(wp[512]);
            wp += G3;
            const ulonglong2* hp = reinterpret_cast<const ulonglong2*>(h_s + k * HSTRIDE);
            ulonglong2 hA = hp[0], hB = hp[1];
            fma2(acc[0], w0, hA.x); fma2(acc[1], w0, hA.y);
            fma2(acc[2], w0, hB.x); fma2(acc[3], w0, hB.y);
            fma2(acc[4], w1, hA.x); fma2(acc[5], w1, hA.y);
            fma2(acc[6], w1, hB.x); fma2(acc[7], w1, hB.y);
            fma2(acc[8], w2, hA.x); fma2(acc[9], w2, hA.y);
            fma2(acc[10], w2, hB.x); fma2(acc[11], w2, hB.y);
        }
        // store the 6 partials the OTHER half needs (its sample pairs)
        {
            const int cp = 2 * (1 - half);
            st[0] = acc[cp];     st[1] = acc[cp + 1];
            st[2] = acc[4 + cp]; st[3] = acc[4 + cp + 1];
            st[4] = acc[8 + cp]; st[5] = acc[8 + cp + 1];
        }

        // head for step i-1 (warps 0-7; h_s stable during phase 1)
        if (warp < NB && i > 0) {
            const int b = warp, t = i - 1;
            float c0 = 0.0f, c1 = 0.0f;
            for (int k = lane; k < NHID; k += 32) {
                float hv = h_s[k * HSTRIDE + b];
                c0 += hv * Dw[2 * k];
                c1 += hv * Dw[2 * k + 1];
            }
#pragma unroll
            for (int off = 16; off > 0; off >>= 1) {
                c0 += __shfl_down_sync(0xffffffffu, c0, off);
                c1 += __shfl_down_sync(0xffffffffu, c1, off);
            }
            if (lane == 0) {
                float la = c0 + db0, lb = c1 + db1;
                float m  = fmaxf(la, lb);
                float ea = expf(la - m), eb = expf(lb - m);
                float sm = ea + eb;
                float lp0 = logf(1e-10f + ea / sm);
                float lp1 = logf(1e-10f + eb / sm);
                float g0 = gum[(t * NB + b) * 2];
                float g1 = gum[(t * NB + b) * 2 + 1];
                int s = (g1 + lp1 > g0 + lp0) ? 1 : 0;   // argmax ties -> index 0
                logP += s ? lp1 : lp0;
                s_arr[b] = s;
                out[(bbase + b) * NSITES + t] = (float)s;
            }
        }
        __syncthreads();   // red ready; s_arr ready; all h reads done

        // ======== phase 2: combine + gate math for my 4 samples ========
        {
            unsigned long long oz0 = ld[0], oz1 = ld[1];
            unsigned long long or0 = ld[2], or1 = ld[3];
            unsigned long long on0 = ld[4], on1 = ld[5];
            unsigned long long sz0, sz1, sr0, sr1, sn0, sn1;
            if (half == 0) {   // own = k-low, other = k-high
                sz0 = add2(acc[op],     oz0); sz1 = add2(acc[op + 1],     oz1);
                sr0 = add2(acc[4 + op], or0); sr1 = add2(acc[4 + op + 1], or1);
                sn0 = add2(acc[8 + op], on0); sn1 = add2(acc[8 + op + 1], on1);
            } else {           // other = k-low first (same order as half 0)
                sz0 = add2(oz0, acc[op]);     sz1 = add2(oz1, acc[op + 1]);
                sr0 = add2(or0, acc[4 + op]); sr1 = add2(or1, acc[4 + op + 1]);
                sn0 = add2(on0, acc[8 + op]); sn1 = add2(on1, acc[8 + op + 1]);
            }
            float gz[4], gr[4], gn[4];
            unpack2(sz0, gz[0], gz[1]); unpack2(sz1, gz[2], gz[3]);
            unpack2(sr0, gr[0], gr[1]); unpack2(sr1, gr[2], gr[3]);
            unpack2(sn0, gn[0], gn[1]); unpack2(sn1, gn[2], gn[3]);

            float4 hold = *reinterpret_cast<float4*>(h_s + j * HSTRIDE + 4 * half);
            float ho[4] = {hold.x, hold.y, hold.z, hold.w};
            float hn4[4];
#pragma unroll
            for (int v = 0; v < 4; ++v) {
                int b = 4 * half + v;
                int sp = s_arr[b];
                float gxz, gxr, gxn;
                if (i == 0) { gxz = b0z; gxr = b0r; gxn = b0n; }
                else if (sp) { gxz = c1z; gxr = c1r; gxn = c1n; }
                else         { gxz = c0z; gxr = c0r; gxn = c0n; }
                float z  = sigmoid_x(gxz + gz[v] + b1z);
                float r  = sigmoid_x(gxr + gr[v] + b1r);
                float hh = tanhf(gxn + r * (gn[v] + b1n));
                hn4[v] = z * ho[v] + (1.0f - z) * hh;
            }
            *reinterpret_cast<float4*>(h_s + j * HSTRIDE + 4 * half) =
                make_float4(hn4[0], hn4[1], hn4[2], hn4[3]);
        }
        __syncthreads();   // h ready for next k-loop / head
    }

    // ======== epilogue head: step NSITES-1 from final h ========
    if (warp < NB) {
        const int b = warp, t = NSITES - 1;
        float c0 = 0.0f, c1 = 0.0f;
        for (int k = lane; k < NHID; k += 32) {
            float hv = h_s[k * HSTRIDE + b];
            c0 += hv * Dw[2 * k];
            c1 += hv * Dw[2 * k + 1];
        }
#pragma unroll
        for (int off = 16; off > 0; off >>= 1) {
            c0 += __shfl_down_sync(0xffffffffu, c0, off);
            c1 += __shfl_down_sync(0xffffffffu, c1, off);
        }
        if (lane == 0) {
            float la = c0 + db0, lb = c1 + db1;
            float m  = fmaxf(la, lb);
            float ea = expf(la - m), eb = expf(lb - m);
            float sm = ea + eb;
            float lp0 = logf(1e-10f + ea / sm);
            float lp1 = logf(1e-10f + eb / sm);
            float g0 = gum[(t * NB + b) * 2];
            float g1 = gum[(t * NB + b) * 2 + 1];
            int s = (g1 + lp1 > g0 + lp0) ? 1 : 0;
            logP += s ? lp1 : lp0;
            out[(bbase + b) * NSITES + t] = (float)s;
            out[BATCH * NSITES + bbase + b] = logP;
        }
    }
}

extern "C" void kernel_launch(void* const* d_in, const int* in_sizes, int n_in,
                              void* d_out, int out_size) {
    (void)in_sizes; (void)n_in; (void)out_size;
    const float* Wx   = (const float*)d_in[0];
    const float* Wh   = (const float*)d_in[1];
    const float* bias = (const float*)d_in[2];
    const float* Dw   = (const float*)d_in[3];
    const float* Db   = (const float*)d_in[4];
    float* out = (float*)d_out;
    rnn_sample_kernel<<<NBLOCKS, THREADS>>>(Wx, Wh, bias, Dw, Db, out);
}

// round 10
// speedup vs baseline: 4.3376x; 1.0014x over previous
#include <cuda_runtime.h>
#include <stdint.h>

#define NSITES   144
#define NHID     256
#define G3       768
#define BATCH    1024
#define NB       8
#define NBLOCKS  (BATCH / NB)
#define THREADS  512
#define KHALF    128
#define HSTRIDE  12                // h_s row stride (floats): 48B rows, 16B-aligned

// ---------------- threefry2x32 core (JAX schedule) ----------------
__device__ __forceinline__ uint32_t rotl32(uint32_t x, uint32_t r) {
    return __funnelshift_l(x, x, r);
}

__device__ __forceinline__ void tf2x32(uint32_t k0, uint32_t k1,
                                       uint32_t x0, uint32_t x1,
                                       uint32_t &o0, uint32_t &o1) {
    uint32_t k2 = k0 ^ k1 ^ 0x1BD11BDAu;
    x0 += k0; x1 += k1;
#define TFR(r) { x0 += x1; x1 = rotl32(x1, r); x1 ^= x0; }
    TFR(13) TFR(15) TFR(26) TFR(6)    x0 += k1; x1 += k2 + 1u;
    TFR(17) TFR(29) TFR(16) TFR(24)   x0 += k2; x1 += k0 + 2u;
    TFR(13) TFR(15) TFR(26) TFR(6)    x0 += k0; x1 += k1 + 3u;
    TFR(17) TFR(29) TFR(16) TFR(24)   x0 += k1; x1 += k2 + 4u;
    TFR(13) TFR(15) TFR(26) TFR(6)    x0 += k2; x1 += k0 + 5u;
#undef TFR
    o0 = x0; o1 = x1;
}

// Partitionable random_bits (32-bit): element i = w0 ^ w1 of tf2x32(key, (0, i))
__device__ __forceinline__ uint32_t rbits_part(uint32_t k0, uint32_t k1, uint32_t i) {
    uint32_t o0, o1;
    tf2x32(k0, k1, 0u, i, o0, o1);
    return o0 ^ o1;
}

// jax.random.gumbel: -log(-log(uniform(tiny, 1)))
__device__ __forceinline__ float gumbel_from(uint32_t bits) {
    const float TINY = 1.17549435e-38f;
    float f = __uint_as_float((bits >> 9) | 0x3f800000u) - 1.0f;
    float u = fmaxf(TINY, f + TINY);
    return -logf(-logf(u));
}

// ---------------- packed f32x2 ops (sm_100+) ----------------
__device__ __forceinline__ void fma2(unsigned long long &d, unsigned long long a,
                                     unsigned long long b) {
    asm("fma.rn.f32x2 %0, %1, %2, %0;" : "+l"(d) : "l"(a), "l"(b));
}
__device__ __forceinline__ unsigned long long pack2(float x) {
    unsigned long long r;
    asm("mov.b64 %0, {%1, %1};" : "=l"(r) : "f"(x));
    return r;
}
__device__ __forceinline__ unsigned long long add2(unsigned long long a,
                                                   unsigned long long b) {
    unsigned long long r;
    asm("add.rn.f32x2 %0, %1, %2;" : "=l"(r) : "l"(a), "l"(b));
    return r;
}
__device__ __forceinline__ void unpack2(unsigned long long v, float &lo, float &hi) {
    asm("mov.b64 {%0, %1}, %2;" : "=f"(lo), "=f"(hi) : "l"(v));
}

__device__ __forceinline__ float sigmoid_x(float x) {
    return 0.5f + 0.5f * tanhf(0.5f * x);
}

__global__ void __launch_bounds__(THREADS, 1)
rnn_sample_kernel(const float* __restrict__ Wx,    // kernel      [2, 768]
                  const float* __restrict__ Wh,    // rec_kernel  [256, 768]
                  const float* __restrict__ bias,  // [2, 768]
                  const float* __restrict__ Dw,    // dense_w     [256, 2]
                  const float* __restrict__ Db,    // dense_b     [2]
                  float* __restrict__ out)         // samples [1024,144] then logP [1024]
{
    __shared__ __align__(16) float h_s[NHID * HSTRIDE];        // 12 KB, [k][b]
    __shared__ __align__(16) unsigned long long red[6][2][NHID]; // 24 KB, [slot][writer-half][j]
    __shared__ float gum[NSITES * NB * 2];                      // 9 KB
    __shared__ int s_arr[NB];

    const int tid  = threadIdx.x;
    const int lane = tid & 31;
    const int warp = tid >> 5;
    const int half = tid >> 8;       // 0: k in [0,128), samples 0-3; 1: k in [128,256), 4-7
    const int j    = tid & 255;      // gate unit / column
    const int bbase = blockIdx.x * NB;

    // ---- one-time init ----
    for (int i = tid; i < NHID * HSTRIDE; i += THREADS) h_s[i] = 0.0f;
    for (int i = tid; i < NSITES * NB * 2; i += THREADS) {
        int t = i >> 4, r = i & 15;
        int b = r >> 1, cls = r & 1;
        uint32_t o0, o1;
        tf2x32(0u, 42u, 0u, (uint32_t)t, o0, o1);       // partitionable split -> step key
        gum[i] = gumbel_from(rbits_part(o0, o1, (uint32_t)(2 * (bbase + b) + cls)));
    }
    if (tid < NB) s_arr[tid] = -1;
    float logP = 0.0f;   // lane 0 of warps 0..7 (sample = warp id)
    __syncthreads();

    // gate-input constants in registers (9): bias row 0 and bias0+Wx[s]
    const float b0z = bias[j],       b0r = bias[256 + j],  b0n = bias[512 + j];
    const float c0z = b0z + Wx[j],        c0r = b0r + Wx[256 + j],  c0n = b0n + Wx[512 + j];
    const float c1z = b0z + Wx[G3 + j],   c1r = b0r + Wx[G3 + 256 + j],
                c1n = b0n + Wx[G3 + 512 + j];
    const float b1z = bias[G3 + j], b1r = bias[G3 + 256 + j], b1n = bias[G3 + 512 + j];
    const float db0 = Db[0], db1 = Db[1];
    const int k0 = half * KHALF;
    const int op = 2 * half;                       // my sample-pair base
    const float* wbase = Wh + k0 * G3 + j;

    // prefetch W rows k0..k0+7 (step-invariant addresses)
    float wa[8], wb[8], wc[8];
#pragma unroll
    for (int p = 0; p < 8; ++p) {
        const float* wq = wbase + p * G3;
        wa[p] = wq[0]; wb[p] = wq[256]; wc[p] = wq[512];
    }

    for (int i = 0; i < NSITES; ++i) {
        // ======== phase 1: k-loop (gh partials) ∥ head for step i-1 ========
        unsigned long long acc[12];
#pragma unroll
        for (int a = 0; a < 12; ++a) acc[a] = 0ull;

        // peeled first 8 k-iters from prefetched W
#pragma unroll
        for (int p = 0; p < 8; ++p) {
            unsigned long long w0 = pack2(wa[p]);
            unsigned long long w1 = pack2(wb[p]);
            unsigned long long w2 = pack2(wc[p]);
            const ulonglong2* hp =
                reinterpret_cast<const ulonglong2*>(h_s + (k0 + p) * HSTRIDE);
            ulonglong2 hA = hp[0], hB = hp[1];
            fma2(acc[0], w0, hA.x); fma2(acc[1], w0, hA.y);
            fma2(acc[2], w0, hB.x); fma2(acc[3], w0, hB.y);
            fma2(acc[4], w1, hA.x); fma2(acc[5], w1, hA.y);
            fma2(acc[6], w1, hB.x); fma2(acc[7], w1, hB.y);
            fma2(acc[8], w2, hA.x); fma2(acc[9], w2, hA.y);
            fma2(acc[10], w2, hB.x); fma2(acc[11], w2, hB.y);
        }

        // main loop k0+8 .. k0+127
        const float* wp = wbase + 8 * G3;
#pragma unroll 8
        for (int k = k0 + 8; k < k0 + KHALF; ++k) {
            unsigned long long w0 = pack2(wp[0]);
            unsigned long long w1 = pack2(wp[256]);
            unsigned long long w2 = pack2(wp[512]);
            wp += G3;
            const ulonglong2* hp = reinterpret_cast<const ulonglong2*>(h_s + k * HSTRIDE);
            ulonglong2 hA = hp[0], hB = hp[1];
            fma2(acc[0], w0, hA.x); fma2(acc[1], w0, hA.y);
            fma2(acc[2], w0, hB.x); fma2(acc[3], w0, hB.y);
            fma2(acc[4], w1, hA.x); fma2(acc[5], w1, hA.y);
            fma2(acc[6], w1, hB.x); fma2(acc[7], w1, hB.y);
            fma2(acc[8], w2, hA.x); fma2(acc[9], w2, hA.y);
            fma2(acc[10], w2, hB.x); fma2(acc[11], w2, hB.y);
        }
        // store the 6 partials the OTHER half needs (conflict-free layout)
        {
            const int cp = 2 * (1 - half);
            red[0][half][j] = acc[cp];     red[1][half][j] = acc[cp + 1];
            red[2][half][j] = acc[4 + cp]; red[3][half][j] = acc[4 + cp + 1];
            red[4][half][j] = acc[8 + cp]; red[5][half][j] = acc[8 + cp + 1];
        }

        // prefetch next step's first W block (L2 hit; hides post-barrier latency)
#pragma unroll
        for (int p = 0; p < 8; ++p) {
            const float* wq = wbase + p * G3;
            wa[p] = wq[0]; wb[p] = wq[256]; wc[p] = wq[512];
        }

        // head for step i-1 (warps 0-7; h_s stable during phase 1)
        if (warp < NB && i > 0) {
            const int b = warp, t = i - 1;
            float c0 = 0.0f, c1 = 0.0f;
            for (int k = lane; k < NHID; k += 32) {
                float hv = h_s[k * HSTRIDE + b];
                c0 += hv * Dw[2 * k];
                c1 += hv * Dw[2 * k + 1];
            }
#pragma unroll
            for (int off = 16; off > 0; off >>= 1) {
                c0 += __shfl_down_sync(0xffffffffu, c0, off);
                c1 += __shfl_down_sync(0xffffffffu, c1, off);
            }
            if (lane == 0) {
                float la = c0 + db0, lb = c1 + db1;
                float m  = fmaxf(la, lb);
                float ea = expf(la - m), eb = expf(lb - m);
                float sm = ea + eb;
                float lp0 = logf(1e-10f + ea / sm);
                float lp1 = logf(1e-10f + eb / sm);
                float g0 = gum[(t * NB + b) * 2];
                float g1 = gum[(t * NB + b) * 2 + 1];
                int s = (g1 + lp1 > g0 + lp0) ? 1 : 0;   // argmax ties -> index 0
                logP += s ? lp1 : lp0;
                s_arr[b] = s;
                out[(bbase + b) * NSITES + t] = (float)s;
            }
        }
        __syncthreads();   // red ready; s_arr ready; all h reads done

        // ======== phase 2: combine + gate math for my 4 samples ========
        {
            const int oh = 1 - half;
            unsigned long long oz0 = red[0][oh][j], oz1 = red[1][oh][j];
            unsigned long long or0 = red[2][oh][j], or1 = red[3][oh][j];
            unsigned long long on0 = red[4][oh][j], on1 = red[5][oh][j];
            unsigned long long sz0, sz1, sr0, sr1, sn0, sn1;
            if (half == 0) {   // own = k-low, other = k-high
                sz0 = add2(acc[op],     oz0); sz1 = add2(acc[op + 1],     oz1);
                sr0 = add2(acc[4 + op], or0); sr1 = add2(acc[4 + op + 1], or1);
                sn0 = add2(acc[8 + op], on0); sn1 = add2(acc[8 + op + 1], on1);
            } else {           // other = k-low first (same order as half 0)
                sz0 = add2(oz0, acc[op]);     sz1 = add2(oz1, acc[op + 1]);
                sr0 = add2(or0, acc[4 + op]); sr1 = add2(or1, acc[4 + op + 1]);
                sn0 = add2(on0, acc[8 + op]); sn1 = add2(on1, acc[8 + op + 1]);
            }
            float gz[4], gr[4], gn[4];
            unpack2(sz0, gz[0], gz[1]); unpack2(sz1, gz[2], gz[3]);
            unpack2(sr0, gr[0], gr[1]); unpack2(sr1, gr[2], gr[3]);
            unpack2(sn0, gn[0], gn[1]); unpack2(sn1, gn[2], gn[3]);

            float4 hold = *reinterpret_cast<float4*>(h_s + j * HSTRIDE + 4 * half);
            float ho[4] = {hold.x, hold.y, hold.z, hold.w};
            float hn4[4];
#pragma unroll
            for (int v = 0; v < 4; ++v) {
                int b = 4 * half + v;
                int sp = s_arr[b];
                float gxz, gxr, gxn;
                if (i == 0) { gxz = b0z; gxr = b0r; gxn = b0n; }
                else if (sp) { gxz = c1z; gxr = c1r; gxn = c1n; }
                else         { gxz = c0z; gxr = c0r; gxn = c0n; }
                float z  = sigmoid_x(gxz + gz[v] + b1z);
                float r  = sigmoid_x(gxr + gr[v] + b1r);
                float hh = tanhf(gxn + r * (gn[v] + b1n));
                hn4[v] = z * ho[v] + (1.0f - z) * hh;
            }
            *reinterpret_cast<float4*>(h_s + j * HSTRIDE + 4 * half) =
                make_float4(hn4[0], hn4[1], hn4[2], hn4[3]);
        }
        __syncthreads();   // h ready for next k-loop / head
    }

    // ======== epilogue head: step NSITES-1 from final h ========
    if (warp < NB) {
        const int b = warp, t = NSITES - 1;
        float c0 = 0.0f, c1 = 0.0f;
        for (int k = lane; k < NHID; k += 32) {
            float hv = h_s[k * HSTRIDE + b];
            c0 += hv * Dw[2 * k];
            c1 += hv * Dw[2 * k + 1];
        }
#pragma unroll
        for (int off = 16; off > 0; off >>= 1) {
            c0 += __shfl_down_sync(0xffffffffu, c0, off);
            c1 += __shfl_down_sync(0xffffffffu, c1, off);
        }
        if (lane == 0) {
            float la = c0 + db0, lb = c1 + db1;
            float m  = fmaxf(la, lb);
            float ea = expf(la - m), eb = expf(lb - m);
            float sm = ea + eb;
            float lp0 = logf(1e-10f + ea / sm);
            float lp1 = logf(1e-10f + eb / sm);
            float g0 = gum[(t * NB + b) * 2];
            float g1 = gum[(t * NB + b) * 2 + 1];
            int s = (g1 + lp1 > g0 + lp0) ? 1 : 0;
            logP += s ? lp1 : lp0;
            out[(bbase + b) * NSITES + t] = (float)s;
            out[BATCH * NSITES + bbase + b] = logP;
        }
    }
}

extern "C" void kernel_launch(void* const* d_in, const int* in_sizes, int n_in,
                              void* d_out, int out_size) {
    (void)in_sizes; (void)n_in; (void)out_size;
    const float* Wx   = (const float*)d_in[0];
    const float* Wh   = (const float*)d_in[1];
    const float* bias = (const float*)d_in[2];
    const float* Dw   = (const float*)d_in[3];
    const float* Db   = (const float*)d_in[4];
    float* out = (float*)d_out;
    rnn_sample_kernel<<<NBLOCKS, THREADS>>>(Wx, Wh, bias, Dw, Db, out);
}